// round 16
// baseline (speedup 1.0000x reference)
#include <cuda_runtime.h>
#include <math.h>
#include <stdint.h>

#define HW    36864      // 192*192
#define CC    512
#define NPTS  36864
#define NND   512
#define KNN   10
#define KK    5
#define MMP   3
#define TOPN  32
#define NBLK  144        // FPS blocks, 256 points each
#define RD    80         // register-cached dims per half (160/point)
#define SC_H  104        // smem-cached dims per half    (208/point)
#define GM_D  72         // streamed dims per half       (144/point)  RD+SC_H+GM_D=256
#define SSTR  212        // smem stride per point (floats): conflict-free LDS.128
#define SC_BYTES (256*SSTR*4)
#define NEG_BIG (-9e15f)

// ---------------- device scratch ----------------
__device__ float    g_norms[NPTS];
__device__ int      g_fps[NND];
__device__ unsigned g_arrive;
__device__ unsigned long long g_slot[NBLK];

__device__ float g_nodes[NND*CC];
__device__ float g_nn[NND*CC];
__device__ float g_sim[NND*NND];
__device__ int   g_tidx[NND*KNN];
__device__ float g_adjW[NND*NND];
__device__ float g_Wh[NND*CC];
__device__ float g_f1[NND];
__device__ float g_f2[NND];
__device__ float g_att[NND*NND];
__device__ float g_gat[NND*CC];
__device__ float g_x[NND*CC];
__device__ float g_xpart[4*CC];
__device__ float g_mean[CC];
__device__ float g_y[CC];
__device__ float g_ref[NND*CC];
__device__ float g_rnorm[NND];
__device__ float g_cqn[KK*CC];
__device__ float g_aqn[MMP*CC];
__device__ float g_aff[KK*NND];
__device__ int   g_top32[KK*TOPN];

__device__ __forceinline__ unsigned ld_acq_u32(const unsigned* p) {
    unsigned v;
    asm volatile("ld.acquire.gpu.u32 %0, [%1];" : "=r"(v) : "l"(p) : "memory");
    return v;
}
__device__ __forceinline__ unsigned long long ld_acq_u64(const unsigned long long* p) {
    unsigned long long v;
    asm volatile("ld.acquire.gpu.u64 %0, [%1];" : "=l"(v) : "l"(p) : "memory");
    return v;
}
__device__ __forceinline__ void st_rel_u64(unsigned long long* p, unsigned long long v) {
    asm volatile("st.release.gpu.u64 [%0], %1;" :: "l"(p), "l"(v) : "memory");
}

// ---------------- FPS ----------------
__global__ void fps_init() { g_arrive = 0u; }
__global__ void dummy_k() { }   // launch-slot padding: keeps fps_kernel in ncu's capture slot

// 144 blocks x 512 threads, 1 block/SM.
// thread = (h = tid>>8, pl = tid&255); point p = bid*256+pl.
// per half (256 dims): [0,80) registers, [80,184) smem cache (POINT-MAJOR -> LDS.128),
//                      [184,256) streamed (MLP-8).
// smem: scache[pl*212 + h*104 + j]  (stride 212: conflict-free 128-bit phases, 16B aligned)
// Barrier: one-hop; warp 0 of every block SEQUENTIALLY HOT-SPINS per slot (R12 discipline).
__global__ void __launch_bounds__(512, 1) fps_kernel(const float* __restrict__ feat) {
    extern __shared__ float scache[];            // [256][212] point-major
    const int tid  = threadIdx.x;
    const int bid  = blockIdx.x;
    const int lane = tid & 31;
    const int wid  = tid >> 5;
    const int pl   = tid & 255;
    const int h    = tid >> 8;
    const int p    = bid * 256 + pl;

    __shared__ float cs[CC];
    __shared__ float sdot[256];
    __shared__ float swv[8];
    __shared__ int   swi[8];
    __shared__ int   s_far;
    __shared__ float s_nfar;

    // ---- fill register cache: dims [h*256, h*256+RD) ----
    float xr[RD];
    {
        const float* fr = feat + (size_t)(h << 8) * HW + p;
#pragma unroll
        for (int d = 0; d < RD; d++) xr[d] = __ldcg(&fr[(size_t)d * HW]);
    }

    // ---- fill SMEM cache: each thread fills its half's 104 rows of its point ----
    {
        float* dst = scache + pl * SSTR + h * SC_H;
        const float* src = feat + (size_t)((h << 8) + RD) * HW + p;
#pragma unroll 4
        for (int j = 0; j < SC_H; j++) dst[j] = __ldcg(&src[(size_t)j * HW]);
    }
    __syncthreads();

    const float* fg  = feat + (size_t)((h << 8) + RD + SC_H) * HW + p;  // streamed base
    const float* scp = scache + pl * SSTR + h * SC_H;                   // smem base (this thread)
    const float* csC = cs + (h << 8);                                   // centroid, this half

    // ---- prologue: squared norms ----
    {
        float a0=0.f,a1=0.f,a2=0.f,a3=0.f;
#pragma unroll
        for (int d = 0; d < RD; d += 4) {
            a0=fmaf(xr[d+0],xr[d+0],a0); a1=fmaf(xr[d+1],xr[d+1],a1);
            a2=fmaf(xr[d+2],xr[d+2],a2); a3=fmaf(xr[d+3],xr[d+3],a3);
        }
#pragma unroll 13
        for (int j = 0; j < SC_H; j += 4) {
            float4 sv = *reinterpret_cast<const float4*>(scp + j);
            a0=fmaf(sv.x,sv.x,a0); a1=fmaf(sv.y,sv.y,a1);
            a2=fmaf(sv.z,sv.z,a2); a3=fmaf(sv.w,sv.w,a3);
        }
#pragma unroll 6
        for (int d = 0; d < GM_D; d += 4) {
            float v0=__ldcg(&fg[(size_t)(d+0)*HW]); float v1=__ldcg(&fg[(size_t)(d+1)*HW]);
            float v2=__ldcg(&fg[(size_t)(d+2)*HW]); float v3=__ldcg(&fg[(size_t)(d+3)*HW]);
            a0=fmaf(v0,v0,a0); a1=fmaf(v1,v1,a1); a2=fmaf(v2,v2,a2); a3=fmaf(v3,v3,a3);
        }
        float part = (a0+a1)+(a2+a3);
        if (h == 1) sdot[pl] = part;
        __syncthreads();
        if (h == 0) g_norms[p] = part + sdot[pl];
    }
    __syncthreads();
    if (tid == 0) {
        __threadfence();
        atomicAdd(&g_arrive, 1u);
        while (ld_acq_u32(&g_arrive) < (unsigned)NBLK) __nanosleep(64);
        __threadfence();
    }
    __syncthreads();

    float nx   = (h == 0) ? __ldcg(&g_norms[p]) : 0.f;
    float minD = 1e10f;
    int   far  = 0;

    for (int it = 0; it < NND; ++it) {
        if (bid == 0 && tid == 0) g_fps[it] = far;

        // centroid features (+ norm) into smem
        cs[tid] = __ldcg(&feat[(size_t)tid * HW + far]);
        if (tid == 0) s_nfar = __ldcg(&g_norms[far]);
        __syncthreads();                                        // sync A

        // ---- dot: streamed dims first (MLP-8), 72 = 9x8 ----
        float b0=0.f,b1=0.f,b2=0.f,b3=0.f,b4=0.f,b5=0.f,b6=0.f,b7=0.f;
#pragma unroll
        for (int d = 0; d < GM_D; d += 8) {
            float4 c0 = *reinterpret_cast<const float4*>(csC + RD + SC_H + d);
            float4 c1 = *reinterpret_cast<const float4*>(csC + RD + SC_H + d + 4);
            float v0=__ldcg(&fg[(size_t)(d+0)*HW]); float v1=__ldcg(&fg[(size_t)(d+1)*HW]);
            float v2=__ldcg(&fg[(size_t)(d+2)*HW]); float v3=__ldcg(&fg[(size_t)(d+3)*HW]);
            float v4=__ldcg(&fg[(size_t)(d+4)*HW]); float v5=__ldcg(&fg[(size_t)(d+5)*HW]);
            float v6=__ldcg(&fg[(size_t)(d+6)*HW]); float v7=__ldcg(&fg[(size_t)(d+7)*HW]);
            b0=fmaf(v0,c0.x,b0); b1=fmaf(v1,c0.y,b1); b2=fmaf(v2,c0.z,b2); b3=fmaf(v3,c0.w,b3);
            b4=fmaf(v4,c1.x,b4); b5=fmaf(v5,c1.y,b5); b6=fmaf(v6,c1.z,b6); b7=fmaf(v7,c1.w,b7);
        }
        // ---- dot: register dims ----
        float a0=0.f,a1=0.f,a2=0.f,a3=0.f;
#pragma unroll
        for (int d = 0; d < RD; d += 4) {
            float4 c = *reinterpret_cast<const float4*>(csC + d);
            a0=fmaf(xr[d+0],c.x,a0); a1=fmaf(xr[d+1],c.y,a1);
            a2=fmaf(xr[d+2],c.z,a2); a3=fmaf(xr[d+3],c.w,a3);
        }
        // ---- dot: smem dims (LDS.128, 26 per thread) ----
#pragma unroll 13
        for (int j = 0; j < SC_H; j += 4) {
            float4 sv = *reinterpret_cast<const float4*>(scp + j);
            float4 c  = *reinterpret_cast<const float4*>(csC + RD + j);
            a0=fmaf(sv.x,c.x,a0); a1=fmaf(sv.y,c.y,a1);
            a2=fmaf(sv.z,c.z,a2); a3=fmaf(sv.w,c.w,a3);
        }
        float part = ((a0+a1)+(a2+a3)) + (((b0+b1)+(b2+b3)) + ((b4+b5)+(b6+b7)));
        if (h == 1) sdot[pl] = part;
        __syncthreads();                                        // sync B

        // ---- half-0: distance + running min + warp argmax ----
        if (h == 0) {
            float dot  = part + sdot[pl];
            float dist = nx + s_nfar - 2.f * dot;
            minD = fminf(minD, dist);
            float v = minD; int ix = p;
#pragma unroll
            for (int o = 16; o > 0; o >>= 1) {
                float ov = __shfl_down_sync(0xffffffffu, v, o);
                int   oi = __shfl_down_sync(0xffffffffu, ix, o);
                if (ov > v || (ov == v && oi < ix)) { v = ov; ix = oi; }
            }
            if (lane == 0) { swv[wid] = v; swi[wid] = ix; }
        }
        __syncthreads();                                        // sync C

        // ---- leader: block best -> release-publish own slot ----
        unsigned long long epoch = (unsigned long long)((it + 1) & 0xFFFF);
        if (tid == 0) {
            float v = swv[0]; int ix = swi[0];
#pragma unroll
            for (int w = 1; w < 8; w++) {
                float ov = swv[w]; int oi = swi[w];
                if (ov > v || (ov == v && oi < ix)) { v = ov; ix = oi; }
            }
            unsigned long long pk = ((unsigned long long)__float_as_uint(v) << 32)
                                  | ((unsigned long long)(unsigned)ix << 16)
                                  | epoch;
            st_rel_u64(&g_slot[bid], pk);
        }

        // ---- one-hop poll: sequential HOT-SPIN per slot (R12 discipline) ----
        if (wid == 0) {
            float v = -3.0e38f; int ix = 0x7fffffff;
            for (int s = lane; s < NBLK; s += 32) {
                unsigned long long w;
                int spins = 0;
                for (;;) {
                    w = ld_acq_u64(&g_slot[s]);
                    if ((w & 0xFFFFull) == epoch) break;
                    if (++spins > 1024) __nanosleep(20);
                }
                float vv = __uint_as_float((unsigned)(w >> 32));
                int   ii = (int)((w >> 16) & 0xFFFFull);
                if (vv > v || (vv == v && ii < ix)) { v = vv; ix = ii; }
            }
#pragma unroll
            for (int o = 16; o > 0; o >>= 1) {
                float ov = __shfl_down_sync(0xffffffffu, v, o);
                int   oi = __shfl_down_sync(0xffffffffu, ix, o);
                if (ov > v || (ov == v && oi < ix)) { v = ov; ix = oi; }
            }
            if (lane == 0) s_far = ix;
        }
        __syncthreads();                                        // sync D
        far = s_far;
    }
}

// ---------------- gather + row-normalize nodes ----------------
__global__ void gather_nodes(const float* __restrict__ feat) {
    __shared__ float red[CC];
    int i = blockIdx.x, tid = threadIdx.x;        // 512 threads
    int idx = g_fps[i];
    float v = feat[(size_t)tid * HW + idx];
    g_nodes[i * CC + tid] = v;
    red[tid] = v * v;
    __syncthreads();
    for (int s = 256; s > 0; s >>= 1) {
        if (tid < s) red[tid] += red[tid + s];
        __syncthreads();
    }
    float inv = 1.f / fmaxf(sqrtf(red[0]), 1e-12f);
    g_nn[i * CC + tid] = v * inv;
}

// ---------------- 64x64 register-blocked GEMMs (512x512x512) ----------------
__global__ void __launch_bounds__(256) gemm_nt64(const float* __restrict__ A,
                                                 const float* __restrict__ B,
                                                 float* __restrict__ Cm) {
    __shared__ float As[16][65], Bs[16][65];
    int tx = threadIdx.x & 15, ty = threadIdx.x >> 4;
    int i0 = blockIdx.y * 64, j0 = blockIdx.x * 64;
    int lr = threadIdx.x >> 2;
    int lk = (threadIdx.x & 3) * 4;
    float acc[4][4] = {};
    for (int k0 = 0; k0 < CC; k0 += 16) {
        float4 av = *reinterpret_cast<const float4*>(&A[(i0 + lr) * CC + k0 + lk]);
        float4 bv = *reinterpret_cast<const float4*>(&B[(j0 + lr) * CC + k0 + lk]);
        As[lk+0][lr]=av.x; As[lk+1][lr]=av.y; As[lk+2][lr]=av.z; As[lk+3][lr]=av.w;
        Bs[lk+0][lr]=bv.x; Bs[lk+1][lr]=bv.y; Bs[lk+2][lr]=bv.z; Bs[lk+3][lr]=bv.w;
        __syncthreads();
#pragma unroll
        for (int kk = 0; kk < 16; kk++) {
            float a0=As[kk][ty*4+0], a1=As[kk][ty*4+1], a2=As[kk][ty*4+2], a3=As[kk][ty*4+3];
            float c0=Bs[kk][tx*4+0], c1=Bs[kk][tx*4+1], c2=Bs[kk][tx*4+2], c3=Bs[kk][tx*4+3];
            acc[0][0]=fmaf(a0,c0,acc[0][0]); acc[0][1]=fmaf(a0,c1,acc[0][1]);
            acc[0][2]=fmaf(a0,c2,acc[0][2]); acc[0][3]=fmaf(a0,c3,acc[0][3]);
            acc[1][0]=fmaf(a1,c0,acc[1][0]); acc[1][1]=fmaf(a1,c1,acc[1][1]);
            acc[1][2]=fmaf(a1,c2,acc[1][2]); acc[1][3]=fmaf(a1,c3,acc[1][3]);
            acc[2][0]=fmaf(a2,c0,acc[2][0]); acc[2][1]=fmaf(a2,c1,acc[2][1]);
            acc[2][2]=fmaf(a2,c2,acc[2][2]); acc[2][3]=fmaf(a2,c3,acc[2][3]);
            acc[3][0]=fmaf(a3,c0,acc[3][0]); acc[3][1]=fmaf(a3,c1,acc[3][1]);
            acc[3][2]=fmaf(a3,c2,acc[3][2]); acc[3][3]=fmaf(a3,c3,acc[3][3]);
        }
        __syncthreads();
    }
#pragma unroll
    for (int u = 0; u < 4; u++)
#pragma unroll
        for (int v = 0; v < 4; v++)
            Cm[(i0 + ty*4 + u) * CC + j0 + tx*4 + v] = acc[u][v];
}

__global__ void __launch_bounds__(256) gemm_nn64(const float* __restrict__ A,
                                                 const float* __restrict__ B,
                                                 float* __restrict__ Cm) {
    __shared__ float As[16][65], Bs[16][65];
    int tx = threadIdx.x & 15, ty = threadIdx.x >> 4;
    int i0 = blockIdx.y * 64, j0 = blockIdx.x * 64;
    int lr = threadIdx.x >> 2;
    int lk = (threadIdx.x & 3) * 4;
    int bk = threadIdx.x >> 4;
    int bj = (threadIdx.x & 15) * 4;
    float acc[4][4] = {};
    for (int k0 = 0; k0 < CC; k0 += 16) {
        float4 av = *reinterpret_cast<const float4*>(&A[(i0 + lr) * CC + k0 + lk]);
        float4 bv = *reinterpret_cast<const float4*>(&B[(k0 + bk) * CC + j0 + bj]);
        As[lk+0][lr]=av.x; As[lk+1][lr]=av.y; As[lk+2][lr]=av.z; As[lk+3][lr]=av.w;
        Bs[bk][bj+0]=bv.x; Bs[bk][bj+1]=bv.y; Bs[bk][bj+2]=bv.z; Bs[bk][bj+3]=bv.w;
        __syncthreads();
#pragma unroll
        for (int kk = 0; kk < 16; kk++) {
            float a0=As[kk][ty*4+0], a1=As[kk][ty*4+1], a2=As[kk][ty*4+2], a3=As[kk][ty*4+3];
            float c0=Bs[kk][tx*4+0], c1=Bs[kk][tx*4+1], c2=Bs[kk][tx*4+2], c3=Bs[kk][tx*4+3];
            acc[0][0]=fmaf(a0,c0,acc[0][0]); acc[0][1]=fmaf(a0,c1,acc[0][1]);
            acc[0][2]=fmaf(a0,c2,acc[0][2]); acc[0][3]=fmaf(a0,c3,acc[0][3]);
            acc[1][0]=fmaf(a1,c0,acc[1][0]); acc[1][1]=fmaf(a1,c1,acc[1][1]);
            acc[1][2]=fmaf(a1,c2,acc[1][2]); acc[1][3]=fmaf(a1,c3,acc[1][3]);
            acc[2][0]=fmaf(a2,c0,acc[2][0]); acc[2][1]=fmaf(a2,c1,acc[2][1]);
            acc[2][2]=fmaf(a2,c2,acc[2][2]); acc[2][3]=fmaf(a2,c3,acc[2][3]);
            acc[3][0]=fmaf(a3,c0,acc[3][0]); acc[3][1]=fmaf(a3,c1,acc[3][1]);
            acc[3][2]=fmaf(a3,c2,acc[3][2]); acc[3][3]=fmaf(a3,c3,acc[3][3]);
        }
        __syncthreads();
    }
#pragma unroll
    for (int u = 0; u < 4; u++)
#pragma unroll
        for (int v = 0; v < 4; v++)
            Cm[(i0 + ty*4 + u) * CC + j0 + tx*4 + v] = acc[u][v];
}

// ---------------- top-10 per row of sim ----------------
__global__ void topk10_k() {
    __shared__ float row[NND];
    __shared__ float rv[128];
    __shared__ int   ri[128];
    int i = blockIdx.x, tid = threadIdx.x;       // 128 threads
    for (int j = tid; j < NND; j += 128) row[j] = g_sim[i * NND + j];
    __syncthreads();
    for (int t = 0; t < KNN; t++) {
        float bv = -3.0e38f; int bi = 0x7fffffff;
        for (int j = tid; j < NND; j += 128) {
            float v = row[j];
            if (v > bv || (v == bv && j < bi)) { bv = v; bi = j; }
        }
        rv[tid] = bv; ri[tid] = bi;
        __syncthreads();
        for (int s = 64; s > 0; s >>= 1) {
            if (tid < s) {
                float ov = rv[tid + s]; int oi = ri[tid + s];
                if (ov > rv[tid] || (ov == rv[tid] && oi < ri[tid])) { rv[tid] = ov; ri[tid] = oi; }
            }
            __syncthreads();
        }
        if (tid == 0) { g_tidx[i * KNN + t] = ri[0]; row[ri[0]] = -3.0e38f; }
        __syncthreads();
    }
}

// ---------------- weighted adjacency ----------------
__global__ void adj_build() {
    __shared__ int ti[KNN];
    int i = blockIdx.x;
    int j = blockIdx.y * 256 + threadIdx.x;
    if (threadIdx.x < KNN) ti[threadIdx.x] = g_tidx[i * KNN + threadIdx.x];
    __syncthreads();
    bool edge = false;
#pragma unroll
    for (int t = 0; t < KNN; t++) edge |= (ti[t] == j);
#pragma unroll
    for (int t = 0; t < KNN; t++) edge |= (g_tidx[j * KNN + t] == i);
    float s = g_sim[i * NND + j];
    g_adjW[i * NND + j] = edge ? s : 0.f;
}

// ---------------- f1/f2 ----------------
__global__ void f12_k(const float* __restrict__ ga) {
    int w = blockIdx.x * 8 + (threadIdx.x >> 5);
    int lane = threadIdx.x & 31;
    float a1 = 0.f, a2 = 0.f;
    for (int c = lane; c < CC; c += 32) {
        float wh = g_Wh[w * CC + c];
        a1 = fmaf(wh, ga[c], a1);
        a2 = fmaf(wh, ga[CC + c], a2);
    }
#pragma unroll
    for (int o = 16; o > 0; o >>= 1) {
        a1 += __shfl_down_sync(0xffffffffu, a1, o);
        a2 += __shfl_down_sync(0xffffffffu, a2, o);
    }
    if (lane == 0) { g_f1[w] = a1; g_f2[w] = a2; }
}

// ---------------- attention row softmax ----------------
__global__ void att_row() {
    __shared__ float f2s[NND];
    __shared__ float red[256];
    int i = blockIdx.x, tid = threadIdx.x;       // 256 threads
    for (int j = tid; j < NND; j += 256) f2s[j] = g_f2[j];
    __syncthreads();
    float fi = g_f1[i];
    int j0 = tid, j1 = tid + 256;
    float w0 = g_adjW[i * NND + j0], w1 = g_adjW[i * NND + j1];
    float e0 = fi + f2s[j0]; e0 = (e0 > 0.f) ? e0 : 0.2f * e0;
    float e1 = fi + f2s[j1]; e1 = (e1 > 0.f) ? e1 : 0.2f * e1;
    float v0 = (w0 > 0.f) ? e0 * w0 : NEG_BIG * w0;
    float v1 = (w1 > 0.f) ? e1 * w1 : NEG_BIG * w1;
    red[tid] = fmaxf(v0, v1);
    __syncthreads();
    for (int s = 128; s > 0; s >>= 1) {
        if (tid < s) red[tid] = fmaxf(red[tid], red[tid + s]);
        __syncthreads();
    }
    float mx = red[0];
    __syncthreads();
    float x0 = expf(v0 - mx), x1 = expf(v1 - mx);
    red[tid] = x0 + x1;
    __syncthreads();
    for (int s = 128; s > 0; s >>= 1) {
        if (tid < s) red[tid] += red[tid + s];
        __syncthreads();
    }
    float inv = 1.f / red[0];
    g_att[i * NND + j0] = x0 * inv;
    g_att[i * NND + j1] = x1 * inv;
}

// ---------------- x = nodes + gat; 4-chunk partial column sums (deterministic) ----
__global__ void xmean_part() {
    int c = (blockIdx.x & 3) * 128 + threadIdx.x;    // column
    int ch = blockIdx.x >> 2;                        // i-chunk 0..3
    int ib = ch * 128;
    float acc = 0.f;
#pragma unroll 8
    for (int i = ib; i < ib + 128; i++) {
        float xv = g_nodes[i * CC + c] + g_gat[i * CC + c];
        g_x[i * CC + c] = xv;
        acc += xv;
    }
    g_xpart[ch * CC + c] = acc;
}
__global__ void xmean_fin() {
    int c = blockIdx.x * 128 + threadIdx.x;          // 4 x 128
    float s = ((g_xpart[c] + g_xpart[CC + c]) + (g_xpart[2*CC + c] + g_xpart[3*CC + c]));
    g_mean[c] = s * (1.f / (float)NND);
}

// ---------------- SE (warp-per-row matvec) ----------------
__global__ void se_k(const float* __restrict__ w1, const float* __restrict__ w2) {
    __shared__ float mv[CC];
    __shared__ float hbuf[128];
    int tid = threadIdx.x, lane = tid & 31, wid = tid >> 5;   // 128 threads
    for (int c = tid; c < CC; c += 128) mv[c] = g_mean[c];
    __syncthreads();
    for (int r = wid; r < 128; r += 4) {
        float acc = 0.f;
        for (int c = lane; c < CC; c += 32) acc = fmaf(w1[r * CC + c], mv[c], acc);
#pragma unroll
        for (int o = 16; o > 0; o >>= 1) acc += __shfl_down_sync(0xffffffffu, acc, o);
        if (lane == 0) hbuf[r] = fmaxf(acc, 0.f);
    }
    __syncthreads();
    for (int c = tid; c < CC; c += 128) {
        float a2 = 0.f;
#pragma unroll 4
        for (int r = 0; r < 128; r++) a2 = fmaf(w2[c * 128 + r], hbuf[r], a2);
        g_y[c] = 1.f / (1.f + expf(-a2));
    }
}

// ---------------- refined = x * y; row norms ----------------
__global__ void refine_k() {
    __shared__ float red[256];
    int i = blockIdx.x, tid = threadIdx.x;       // 256 threads
    float v0 = g_x[i * CC + tid] * g_y[tid];
    float v1 = g_x[i * CC + tid + 256] * g_y[tid + 256];
    g_ref[i * CC + tid] = v0;
    g_ref[i * CC + tid + 256] = v1;
    red[tid] = v0 * v0 + v1 * v1;
    __syncthreads();
    for (int s = 128; s > 0; s >>= 1) {
        if (tid < s) red[tid] += red[tid + s];
        __syncthreads();
    }
    if (tid == 0) g_rnorm[i] = fmaxf(sqrtf(red[0]), 1e-12f);
}

// ---------------- normalize query vectors ----------------
__global__ void normq_k(const float* __restrict__ cq, const float* __restrict__ aq) {
    __shared__ float red[CC];
    int b = blockIdx.x, tid = threadIdx.x;       // 8 x 512
    const float* src = (b < KK) ? (cq + b * CC) : (aq + (b - KK) * CC);
    float* dst = (b < KK) ? (g_cqn + b * CC) : (g_aqn + (b - KK) * CC);
    float v = src[tid];
    red[tid] = v * v;
    __syncthreads();
    for (int s = 256; s > 0; s >>= 1) {
        if (tid < s) red[tid] += red[tid + s];
        __syncthreads();
    }
    dst[tid] = v / fmaxf(sqrtf(red[0]), 1e-12f);
}

// ---------------- aff[k][n] = cqn[k] . rn[n] ----------------
__global__ void aff_k() {
    int g = blockIdx.x * 8 + (threadIdx.x >> 5); // 320 blocks x 8 warps = 2560
    int lane = threadIdx.x & 31;
    int k = g / NND, n = g % NND;
    float acc = 0.f;
    for (int c = lane; c < CC; c += 32) acc = fmaf(g_cqn[k * CC + c], g_ref[n * CC + c], acc);
#pragma unroll
    for (int o = 16; o > 0; o >>= 1) acc += __shfl_down_sync(0xffffffffu, acc, o);
    if (lane == 0) g_aff[k * NND + n] = acc / g_rnorm[n];
}

// ---------------- canonical prototypes -> out[0:2560] ----------------
__global__ void canon_k(float* __restrict__ out) {
    __shared__ float w[NND];
    __shared__ float red[256];
    int k = blockIdx.x, tid = threadIdx.x;       // 256 threads
    float v0 = g_aff[k * NND + tid], v1 = g_aff[k * NND + tid + 256];
    red[tid] = fmaxf(v0, v1);
    __syncthreads();
    for (int s = 128; s > 0; s >>= 1) {
        if (tid < s) red[tid] = fmaxf(red[tid], red[tid + s]);
        __syncthreads();
    }
    float mx = red[0];
    __syncthreads();
    float e0 = expf(v0 - mx), e1 = expf(v1 - mx);
    red[tid] = e0 + e1;
    __syncthreads();
    for (int s = 128; s > 0; s >>= 1) {
        if (tid < s) red[tid] += red[tid + s];
        __syncthreads();
    }
    float inv = 1.f / red[0];
    w[tid] = e0 * inv; w[tid + 256] = e1 * inv;
    __syncthreads();
    float a0 = 0.f, a1 = 0.f;
#pragma unroll 4
    for (int n = 0; n < NND; n++) {
        float wn = w[n];
        a0 = fmaf(wn, g_ref[n * CC + tid], a0);
        a1 = fmaf(wn, g_ref[n * CC + tid + 256], a1);
    }
    out[k * CC + tid] = a0;
    out[k * CC + tid + 256] = a1;
}

// ---------------- top-32 per archetype ----------------
__global__ void top32_k() {
    __shared__ float row[NND];
    __shared__ float rv[128];
    __shared__ int   ri[128];
    int k = blockIdx.x, tid = threadIdx.x;       // 128 threads
    for (int j = tid; j < NND; j += 128) row[j] = g_aff[k * NND + j];
    __syncthreads();
    for (int t = 0; t < TOPN; t++) {
        float bv = -3.0e38f; int bi = 0x7fffffff;
        for (int j = tid; j < NND; j += 128) {
            float v = row[j];
            if (v > bv || (v == bv && j < bi)) { bv = v; bi = j; }
        }
        rv[tid] = bv; ri[tid] = bi;
        __syncthreads();
        for (int s = 64; s > 0; s >>= 1) {
            if (tid < s) {
                float ov = rv[tid + s]; int oi = ri[tid + s];
                if (ov > rv[tid] || (ov == rv[tid] && oi < ri[tid])) { rv[tid] = ov; ri[tid] = oi; }
            }
            __syncthreads();
        }
        if (tid == 0) { g_top32[k * TOPN + t] = ri[0]; row[ri[0]] = -3.0e38f; }
        __syncthreads();
    }
}

// ---------------- appearance prototypes -> out[2560:10240] ----------------
__global__ void app_k(float* __restrict__ out) {
    __shared__ int   tops[TOPN];
    __shared__ float wv[TOPN];
    __shared__ float probs[TOPN];
    int k = blockIdx.x / MMP, m = blockIdx.x % MMP;
    int tid = threadIdx.x;                        // 256 threads
    int wid = tid >> 5, lane = tid & 31;
    if (tid < TOPN) tops[tid] = g_top32[k * TOPN + tid];
    __syncthreads();
    for (int t = wid; t < TOPN; t += 8) {
        int n = tops[t];
        float acc = 0.f;
        for (int c = lane; c < CC; c += 32) acc = fmaf(g_aqn[m * CC + c], g_ref[n * CC + c], acc);
#pragma unroll
        for (int o = 16; o > 0; o >>= 1) acc += __shfl_down_sync(0xffffffffu, acc, o);
        if (lane == 0) wv[t] = acc / g_rnorm[n];
    }
    __syncthreads();
    if (tid < 32) {
        float v = wv[tid];
        float mx = v;
#pragma unroll
        for (int o = 16; o > 0; o >>= 1) mx = fmaxf(mx, __shfl_xor_sync(0xffffffffu, mx, o));
        float e = expf(v - mx);
        float s = e;
#pragma unroll
        for (int o = 16; o > 0; o >>= 1) s += __shfl_xor_sync(0xffffffffu, s, o);
        probs[tid] = e / s;
    }
    __syncthreads();
    float a0 = 0.f, a1 = 0.f;
    for (int t = 0; t < TOPN; t++) {
        int n = tops[t];
        float pb = probs[t];
        a0 = fmaf(pb, g_ref[n * CC + tid], a0);
        a1 = fmaf(pb, g_ref[n * CC + tid + 256], a1);
    }
    int base = KK * CC + (k * MMP + m) * CC;
    out[base + tid] = a0;
    out[base + tid + 256] = a1;
}

__global__ void tail_k(float* __restrict__ out, int out_size) {
    if (out_size > KK * CC + KK * MMP * CC) out[KK * CC + KK * MMP * CC] = 0.f;
}

// ---------------- launcher ----------------
extern "C" void kernel_launch(void* const* d_in, const int* in_sizes, int n_in,
                              void* d_out, int out_size) {
    const float* feat = (const float*)d_in[0];
    const float* cq   = (const float*)d_in[3];
    const float* aq   = (const float*)d_in[4];
    const float* gatW = (const float*)d_in[5];
    const float* gata = (const float*)d_in[6];
    const float* sew1 = (const float*)d_in[7];
    const float* sew2 = (const float*)d_in[8];
    float* out = (float*)d_out;

    float *p_nn, *p_sim, *p_nodes, *p_Wh, *p_att, *p_gat;
    cudaGetSymbolAddress((void**)&p_nn, g_nn);
    cudaGetSymbolAddress((void**)&p_sim, g_sim);
    cudaGetSymbolAddress((void**)&p_nodes, g_nodes);
    cudaGetSymbolAddress((void**)&p_Wh, g_Wh);
    cudaGetSymbolAddress((void**)&p_att, g_att);
    cudaGetSymbolAddress((void**)&p_gat, g_gat);

    cudaFuncSetAttribute(fps_kernel, cudaFuncAttributeMaxDynamicSharedMemorySize, SC_BYTES);

    dim3 g64(8, 8);

    // launch order tuned so ncu's capture slot hits fps_kernel
    fps_init<<<1, 1>>>();
    dummy_k<<<1, 1>>>();
    dummy_k<<<1, 1>>>();
    fps_kernel<<<NBLK, 512, SC_BYTES>>>(feat);
    gather_nodes<<<NND, 512>>>(feat);
    gemm_nt64<<<g64, 256>>>(p_nn, p_nn, p_sim);
    topk10_k<<<NND, 128>>>();
    adj_build<<<dim3(NND, 2), 256>>>();
    gemm_nt64<<<g64, 256>>>(p_nodes, gatW, p_Wh);
    f12_k<<<64, 256>>>(gata);
    att_row<<<NND, 256>>>();
    gemm_nn64<<<g64, 256>>>(p_att, p_Wh, p_gat);
    xmean_part<<<16, 128>>>();
    xmean_fin<<<4, 128>>>();
    se_k<<<1, 128>>>(sew1, sew2);
    refine_k<<<NND, 256>>>();
    normq_k<<<8, 512>>>(cq, aq);
    aff_k<<<320, 256>>>();
    canon_k<<<KK, 256>>>(out);
    top32_k<<<KK, 128>>>();
    app_k<<<KK * MMP, 256>>>(out);
    tail_k<<<1, 1>>>(out, out_size);
}

// round 17
// speedup vs baseline: 1.2532x; 1.2532x over previous
#include <cuda_runtime.h>
#include <math.h>
#include <stdint.h>

#define HW    36864      // 192*192
#define CC    512
#define NPTS  36864
#define NND   512
#define KNN   10
#define KK    5
#define MMP   3
#define TOPN  32
#define NBLK  144        // FPS blocks, 256 points each
#define RD    80         // register-cached dims per half (160/point)
#define SC_H  108        // smem-cached dims per half    (216/point)
#define GM_D  68         // streamed dims per half       (136/point)  RD+SC_H+GM_D=256
#define SC_BYTES (216*256*4)
#define NEG_BIG (-9e15f)

// ---------------- device scratch ----------------
__device__ float    g_norms[NPTS];
__device__ int      g_fps[NND];
__device__ unsigned g_arrive;
__device__ unsigned long long g_slot[NBLK];

__device__ float g_nodes[NND*CC];
__device__ float g_nn[NND*CC];
__device__ float g_sim[NND*NND];
__device__ int   g_tidx[NND*KNN];
__device__ float g_adjW[NND*NND];
__device__ float g_Wh[NND*CC];
__device__ float g_f1[NND];
__device__ float g_f2[NND];
__device__ float g_att[NND*NND];
__device__ float g_gat[NND*CC];
__device__ float g_x[NND*CC];
__device__ float g_mean[CC];
__device__ float g_y[CC];
__device__ float g_ref[NND*CC];
__device__ float g_rnorm[NND];
__device__ float g_cqn[KK*CC];
__device__ float g_aqn[MMP*CC];
__device__ float g_aff[KK*NND];
__device__ int   g_top32[KK*TOPN];

__device__ __forceinline__ unsigned ld_acq_u32(const unsigned* p) {
    unsigned v;
    asm volatile("ld.acquire.gpu.u32 %0, [%1];" : "=r"(v) : "l"(p) : "memory");
    return v;
}
__device__ __forceinline__ unsigned long long ld_acq_u64(const unsigned long long* p) {
    unsigned long long v;
    asm volatile("ld.acquire.gpu.u64 %0, [%1];" : "=l"(v) : "l"(p) : "memory");
    return v;
}
__device__ __forceinline__ void st_rel_u64(unsigned long long* p, unsigned long long v) {
    asm volatile("st.release.gpu.u64 [%0], %1;" :: "l"(p), "l"(v) : "memory");
}

// ---------------- FPS ----------------
__global__ void fps_init() { g_arrive = 0u; }
__global__ void dummy_k() { }   // launch-slot padding: keeps fps_kernel in ncu's capture slot

// 144 blocks x 512 threads, 1 block/SM.
// per half (256 dims): [0,80) registers, [80,188) smem cache (dim-major), [188,256) streamed.
// Barrier: one-hop. Every block release-publishes its slot; every block's warp 0 polls
// all 144 slots sequentially with HOT-SPIN per slot, reduces in-warp, broadcasts via smem.
__global__ void __launch_bounds__(512, 1) fps_kernel(const float* __restrict__ feat) {
    extern __shared__ float scache[];            // [216][256] dim-major
    const int tid  = threadIdx.x;
    const int bid  = blockIdx.x;
    const int lane = tid & 31;
    const int wid  = tid >> 5;
    const int pl   = tid & 255;
    const int h    = tid >> 8;
    const int p    = bid * 256 + pl;

    __shared__ float cs[CC];
    __shared__ float sdot[256];
    __shared__ float swv[8];
    __shared__ int   swi[8];
    __shared__ int   s_far;
    __shared__ float s_nfar;

    // ---- fill register cache: dims [h*256, h*256+RD) ----
    float xr[RD];
    {
        const float* fr = feat + (size_t)(h << 8) * HW + p;
#pragma unroll
        for (int d = 0; d < RD; d++) xr[d] = __ldcg(&fr[(size_t)d * HW]);
    }

    // ---- fill SMEM cache: 216 rows, 2 rows per pass ----
    for (int r0 = 0; r0 < 216; r0 += 2) {
        int r  = r0 + h;
        int gd = (r < SC_H) ? (RD + r) : (256 + RD + (r - SC_H));
        scache[r * 256 + pl] = __ldcg(&feat[(size_t)gd * HW + p]);
    }
    __syncthreads();   // prologue reads rows written by the other half

    const float* fg  = feat + (size_t)((h << 8) + RD + SC_H) * HW + p;  // streamed base
    const float* sc  = scache + (h * SC_H) * 256 + pl;                  // smem base
    const float* csC = cs + (h << 8);                                   // centroid, this half

    // ---- prologue: squared norms ----
    {
        float a0=0.f,a1=0.f,a2=0.f,a3=0.f;
#pragma unroll
        for (int d = 0; d < RD; d += 4) {
            a0=fmaf(xr[d+0],xr[d+0],a0); a1=fmaf(xr[d+1],xr[d+1],a1);
            a2=fmaf(xr[d+2],xr[d+2],a2); a3=fmaf(xr[d+3],xr[d+3],a3);
        }
#pragma unroll 4
        for (int j = 0; j < SC_H; j += 4) {
            float v0=sc[(j+0)*256], v1=sc[(j+1)*256], v2=sc[(j+2)*256], v3=sc[(j+3)*256];
            a0=fmaf(v0,v0,a0); a1=fmaf(v1,v1,a1); a2=fmaf(v2,v2,a2); a3=fmaf(v3,v3,a3);
        }
#pragma unroll 4
        for (int d = 0; d < GM_D; d += 4) {
            float v0=__ldcg(&fg[(size_t)(d+0)*HW]); float v1=__ldcg(&fg[(size_t)(d+1)*HW]);
            float v2=__ldcg(&fg[(size_t)(d+2)*HW]); float v3=__ldcg(&fg[(size_t)(d+3)*HW]);
            a0=fmaf(v0,v0,a0); a1=fmaf(v1,v1,a1); a2=fmaf(v2,v2,a2); a3=fmaf(v3,v3,a3);
        }
        float part = (a0+a1)+(a2+a3);
        if (h == 1) sdot[pl] = part;
        __syncthreads();
        if (h == 0) g_norms[p] = part + sdot[pl];
    }
    __syncthreads();
    if (tid == 0) {
        __threadfence();
        atomicAdd(&g_arrive, 1u);
        while (ld_acq_u32(&g_arrive) < (unsigned)NBLK) __nanosleep(64);
        __threadfence();
    }
    __syncthreads();

    float nx   = (h == 0) ? __ldcg(&g_norms[p]) : 0.f;
    float minD = 1e10f;
    int   far  = 0;

    for (int it = 0; it < NND; ++it) {
        if (bid == 0 && tid == 0) g_fps[it] = far;

        // centroid features (+ norm) into smem
        cs[tid] = __ldcg(&feat[(size_t)tid * HW + far]);
        if (tid == 0) s_nfar = __ldcg(&g_norms[far]);
        __syncthreads();                                        // sync A

        // ---- dot: streamed dims first (MLP-8) ----
        float b0=0.f,b1=0.f,b2=0.f,b3=0.f,b4=0.f,b5=0.f,b6=0.f,b7=0.f;
#pragma unroll
        for (int d = 0; d < 64; d += 8) {
            float4 c0 = *reinterpret_cast<const float4*>(csC + RD + SC_H + d);
            float4 c1 = *reinterpret_cast<const float4*>(csC + RD + SC_H + d + 4);
            float v0=__ldcg(&fg[(size_t)(d+0)*HW]); float v1=__ldcg(&fg[(size_t)(d+1)*HW]);
            float v2=__ldcg(&fg[(size_t)(d+2)*HW]); float v3=__ldcg(&fg[(size_t)(d+3)*HW]);
            float v4=__ldcg(&fg[(size_t)(d+4)*HW]); float v5=__ldcg(&fg[(size_t)(d+5)*HW]);
            float v6=__ldcg(&fg[(size_t)(d+6)*HW]); float v7=__ldcg(&fg[(size_t)(d+7)*HW]);
            b0=fmaf(v0,c0.x,b0); b1=fmaf(v1,c0.y,b1); b2=fmaf(v2,c0.z,b2); b3=fmaf(v3,c0.w,b3);
            b4=fmaf(v4,c1.x,b4); b5=fmaf(v5,c1.y,b5); b6=fmaf(v6,c1.z,b6); b7=fmaf(v7,c1.w,b7);
        }
        {   // tail dims 64..67
            float4 c = *reinterpret_cast<const float4*>(csC + RD + SC_H + 64);
            float v0=__ldcg(&fg[(size_t)64*HW]); float v1=__ldcg(&fg[(size_t)65*HW]);
            float v2=__ldcg(&fg[(size_t)66*HW]); float v3=__ldcg(&fg[(size_t)67*HW]);
            b0=fmaf(v0,c.x,b0); b1=fmaf(v1,c.y,b1); b2=fmaf(v2,c.z,b2); b3=fmaf(v3,c.w,b3);
        }
        // ---- dot: register dims ----
        float a0=0.f,a1=0.f,a2=0.f,a3=0.f;
#pragma unroll
        for (int d = 0; d < RD; d += 4) {
            float4 c = *reinterpret_cast<const float4*>(csC + d);
            a0=fmaf(xr[d+0],c.x,a0); a1=fmaf(xr[d+1],c.y,a1);
            a2=fmaf(xr[d+2],c.z,a2); a3=fmaf(xr[d+3],c.w,a3);
        }
        // ---- dot: smem dims ----
#pragma unroll 4
        for (int j = 0; j < SC_H; j += 4) {
            float4 c = *reinterpret_cast<const float4*>(csC + RD + j);
            a0=fmaf(sc[(j+0)*256],c.x,a0); a1=fmaf(sc[(j+1)*256],c.y,a1);
            a2=fmaf(sc[(j+2)*256],c.z,a2); a3=fmaf(sc[(j+3)*256],c.w,a3);
        }
        float part = ((a0+a1)+(a2+a3)) + (((b0+b1)+(b2+b3)) + ((b4+b5)+(b6+b7)));
        if (h == 1) sdot[pl] = part;
        __syncthreads();                                        // sync B

        // ---- half-0: distance + running min + warp argmax ----
        if (h == 0) {
            float dot  = part + sdot[pl];
            float dist = nx + s_nfar - 2.f * dot;
            minD = fminf(minD, dist);
            float v = minD; int ix = p;
#pragma unroll
            for (int o = 16; o > 0; o >>= 1) {
                float ov = __shfl_down_sync(0xffffffffu, v, o);
                int   oi = __shfl_down_sync(0xffffffffu, ix, o);
                if (ov > v || (ov == v && oi < ix)) { v = ov; ix = oi; }
            }
            if (lane == 0) { swv[wid] = v; swi[wid] = ix; }
        }
        __syncthreads();                                        // sync C

        // ---- leader: block best -> release-publish own slot ----
        unsigned long long epoch = (unsigned long long)((it + 1) & 0xFFFF);
        if (tid == 0) {
            float v = swv[0]; int ix = swi[0];
#pragma unroll
            for (int w = 1; w < 8; w++) {
                float ov = swv[w]; int oi = swi[w];
                if (ov > v || (ov == v && oi < ix)) { v = ov; ix = oi; }
            }
            unsigned long long pk = ((unsigned long long)__float_as_uint(v) << 32)
                                  | ((unsigned long long)(unsigned)ix << 16)
                                  | epoch;
            st_rel_u64(&g_slot[bid], pk);
        }

        // ---- one-hop poll: warp 0 of EVERY block polls all 144 slots (hot-spin) ----
        if (wid == 0) {
            float v = -3.0e38f; int ix = 0x7fffffff;
            for (int s = lane; s < NBLK; s += 32) {
                unsigned long long w;
                int spins = 0;
                for (;;) {
                    w = ld_acq_u64(&g_slot[s]);
                    if ((w & 0xFFFFull) == epoch) break;
                    if (++spins > 1024) __nanosleep(20);
                }
                float vv = __uint_as_float((unsigned)(w >> 32));
                int   ii = (int)((w >> 16) & 0xFFFFull);
                if (vv > v || (vv == v && ii < ix)) { v = vv; ix = ii; }
            }
#pragma unroll
            for (int o = 16; o > 0; o >>= 1) {
                float ov = __shfl_down_sync(0xffffffffu, v, o);
                int   oi = __shfl_down_sync(0xffffffffu, ix, o);
                if (ov > v || (ov == v && oi < ix)) { v = ov; ix = oi; }
            }
            if (lane == 0) s_far = ix;
        }
        __syncthreads();                                        // sync D
        far = s_far;
    }
}

// ---------------- gather + row-normalize nodes ----------------
__global__ void gather_nodes(const float* __restrict__ feat) {
    __shared__ float red[CC];
    int i = blockIdx.x, tid = threadIdx.x;        // 512 threads
    int idx = g_fps[i];
    float v = feat[(size_t)tid * HW + idx];
    g_nodes[i * CC + tid] = v;
    red[tid] = v * v;
    __syncthreads();
    for (int s = 256; s > 0; s >>= 1) {
        if (tid < s) red[tid] += red[tid + s];
        __syncthreads();
    }
    float inv = 1.f / fmaxf(sqrtf(red[0]), 1e-12f);
    g_nn[i * CC + tid] = v * inv;
}

// ---------------- 64x64 register-blocked GEMMs (512x512x512) ----------------
__global__ void __launch_bounds__(256) gemm_nt64(const float* __restrict__ A,
                                                 const float* __restrict__ B,
                                                 float* __restrict__ Cm) {
    __shared__ float As[16][65], Bs[16][65];
    int tx = threadIdx.x & 15, ty = threadIdx.x >> 4;
    int i0 = blockIdx.y * 64, j0 = blockIdx.x * 64;
    int lr = threadIdx.x >> 2;
    int lk = (threadIdx.x & 3) * 4;
    float acc[4][4] = {};
    for (int k0 = 0; k0 < CC; k0 += 16) {
        float4 av = *reinterpret_cast<const float4*>(&A[(i0 + lr) * CC + k0 + lk]);
        float4 bv = *reinterpret_cast<const float4*>(&B[(j0 + lr) * CC + k0 + lk]);
        As[lk+0][lr]=av.x; As[lk+1][lr]=av.y; As[lk+2][lr]=av.z; As[lk+3][lr]=av.w;
        Bs[lk+0][lr]=bv.x; Bs[lk+1][lr]=bv.y; Bs[lk+2][lr]=bv.z; Bs[lk+3][lr]=bv.w;
        __syncthreads();
#pragma unroll
        for (int kk = 0; kk < 16; kk++) {
            float a0=As[kk][ty*4+0], a1=As[kk][ty*4+1], a2=As[kk][ty*4+2], a3=As[kk][ty*4+3];
            float c0=Bs[kk][tx*4+0], c1=Bs[kk][tx*4+1], c2=Bs[kk][tx*4+2], c3=Bs[kk][tx*4+3];
            acc[0][0]=fmaf(a0,c0,acc[0][0]); acc[0][1]=fmaf(a0,c1,acc[0][1]);
            acc[0][2]=fmaf(a0,c2,acc[0][2]); acc[0][3]=fmaf(a0,c3,acc[0][3]);
            acc[1][0]=fmaf(a1,c0,acc[1][0]); acc[1][1]=fmaf(a1,c1,acc[1][1]);
            acc[1][2]=fmaf(a1,c2,acc[1][2]); acc[1][3]=fmaf(a1,c3,acc[1][3]);
            acc[2][0]=fmaf(a2,c0,acc[2][0]); acc[2][1]=fmaf(a2,c1,acc[2][1]);
            acc[2][2]=fmaf(a2,c2,acc[2][2]); acc[2][3]=fmaf(a2,c3,acc[2][3]);
            acc[3][0]=fmaf(a3,c0,acc[3][0]); acc[3][1]=fmaf(a3,c1,acc[3][1]);
            acc[3][2]=fmaf(a3,c2,acc[3][2]); acc[3][3]=fmaf(a3,c3,acc[3][3]);
        }
        __syncthreads();
    }
#pragma unroll
    for (int u = 0; u < 4; u++)
#pragma unroll
        for (int v = 0; v < 4; v++)
            Cm[(i0 + ty*4 + u) * CC + j0 + tx*4 + v] = acc[u][v];
}

__global__ void __launch_bounds__(256) gemm_nn64(const float* __restrict__ A,
                                                 const float* __restrict__ B,
                                                 float* __restrict__ Cm) {
    __shared__ float As[16][65], Bs[16][65];
    int tx = threadIdx.x & 15, ty = threadIdx.x >> 4;
    int i0 = blockIdx.y * 64, j0 = blockIdx.x * 64;
    int lr = threadIdx.x >> 2;
    int lk = (threadIdx.x & 3) * 4;
    int bk = threadIdx.x >> 4;
    int bj = (threadIdx.x & 15) * 4;
    float acc[4][4] = {};
    for (int k0 = 0; k0 < CC; k0 += 16) {
        float4 av = *reinterpret_cast<const float4*>(&A[(i0 + lr) * CC + k0 + lk]);
        float4 bv = *reinterpret_cast<const float4*>(&B[(k0 + bk) * CC + j0 + bj]);
        As[lk+0][lr]=av.x; As[lk+1][lr]=av.y; As[lk+2][lr]=av.z; As[lk+3][lr]=av.w;
        Bs[bk][bj+0]=bv.x; Bs[bk][bj+1]=bv.y; Bs[bk][bj+2]=bv.z; Bs[bk][bj+3]=bv.w;
        __syncthreads();
#pragma unroll
        for (int kk = 0; kk < 16; kk++) {
            float a0=As[kk][ty*4+0], a1=As[kk][ty*4+1], a2=As[kk][ty*4+2], a3=As[kk][ty*4+3];
            float c0=Bs[kk][tx*4+0], c1=Bs[kk][tx*4+1], c2=Bs[kk][tx*4+2], c3=Bs[kk][tx*4+3];
            acc[0][0]=fmaf(a0,c0,acc[0][0]); acc[0][1]=fmaf(a0,c1,acc[0][1]);
            acc[0][2]=fmaf(a0,c2,acc[0][2]); acc[0][3]=fmaf(a0,c3,acc[0][3]);
            acc[1][0]=fmaf(a1,c0,acc[1][0]); acc[1][1]=fmaf(a1,c1,acc[1][1]);
            acc[1][2]=fmaf(a1,c2,acc[1][2]); acc[1][3]=fmaf(a1,c3,acc[1][3]);
            acc[2][0]=fmaf(a2,c0,acc[2][0]); acc[2][1]=fmaf(a2,c1,acc[2][1]);
            acc[2][2]=fmaf(a2,c2,acc[2][2]); acc[2][3]=fmaf(a2,c3,acc[2][3]);
            acc[3][0]=fmaf(a3,c0,acc[3][0]); acc[3][1]=fmaf(a3,c1,acc[3][1]);
            acc[3][2]=fmaf(a3,c2,acc[3][2]); acc[3][3]=fmaf(a3,c3,acc[3][3]);
        }
        __syncthreads();
    }
#pragma unroll
    for (int u = 0; u < 4; u++)
#pragma unroll
        for (int v = 0; v < 4; v++)
            Cm[(i0 + ty*4 + u) * CC + j0 + tx*4 + v] = acc[u][v];
}

// ---------------- top-10 per row of sim ----------------
__global__ void topk10_k() {
    __shared__ float row[NND];
    __shared__ float rv[128];
    __shared__ int   ri[128];
    int i = blockIdx.x, tid = threadIdx.x;       // 128 threads
    for (int j = tid; j < NND; j += 128) row[j] = g_sim[i * NND + j];
    __syncthreads();
    for (int t = 0; t < KNN; t++) {
        float bv = -3.0e38f; int bi = 0x7fffffff;
        for (int j = tid; j < NND; j += 128) {
            float v = row[j];
            if (v > bv || (v == bv && j < bi)) { bv = v; bi = j; }
        }
        rv[tid] = bv; ri[tid] = bi;
        __syncthreads();
        for (int s = 64; s > 0; s >>= 1) {
            if (tid < s) {
                float ov = rv[tid + s]; int oi = ri[tid + s];
                if (ov > rv[tid] || (ov == rv[tid] && oi < ri[tid])) { rv[tid] = ov; ri[tid] = oi; }
            }
            __syncthreads();
        }
        if (tid == 0) { g_tidx[i * KNN + t] = ri[0]; row[ri[0]] = -3.0e38f; }
        __syncthreads();
    }
}

// ---------------- weighted adjacency ----------------
__global__ void adj_build() {
    __shared__ int ti[KNN];
    int i = blockIdx.x;
    int j = blockIdx.y * 256 + threadIdx.x;
    if (threadIdx.x < KNN) ti[threadIdx.x] = g_tidx[i * KNN + threadIdx.x];
    __syncthreads();
    bool edge = false;
#pragma unroll
    for (int t = 0; t < KNN; t++) edge |= (ti[t] == j);
#pragma unroll
    for (int t = 0; t < KNN; t++) edge |= (g_tidx[j * KNN + t] == i);
    float s = g_sim[i * NND + j];
    g_adjW[i * NND + j] = edge ? s : 0.f;
}

// ---------------- f1/f2 ----------------
__global__ void f12_k(const float* __restrict__ ga) {
    int w = blockIdx.x * 8 + (threadIdx.x >> 5);
    int lane = threadIdx.x & 31;
    float a1 = 0.f, a2 = 0.f;
    for (int c = lane; c < CC; c += 32) {
        float wh = g_Wh[w * CC + c];
        a1 = fmaf(wh, ga[c], a1);
        a2 = fmaf(wh, ga[CC + c], a2);
    }
#pragma unroll
    for (int o = 16; o > 0; o >>= 1) {
        a1 += __shfl_down_sync(0xffffffffu, a1, o);
        a2 += __shfl_down_sync(0xffffffffu, a2, o);
    }
    if (lane == 0) { g_f1[w] = a1; g_f2[w] = a2; }
}

// ---------------- attention row softmax ----------------
__global__ void att_row() {
    __shared__ float f2s[NND];
    __shared__ float red[256];
    int i = blockIdx.x, tid = threadIdx.x;       // 256 threads
    for (int j = tid; j < NND; j += 256) f2s[j] = g_f2[j];
    __syncthreads();
    float fi = g_f1[i];
    int j0 = tid, j1 = tid + 256;
    float w0 = g_adjW[i * NND + j0], w1 = g_adjW[i * NND + j1];
    float e0 = fi + f2s[j0]; e0 = (e0 > 0.f) ? e0 : 0.2f * e0;
    float e1 = fi + f2s[j1]; e1 = (e1 > 0.f) ? e1 : 0.2f * e1;
    float v0 = (w0 > 0.f) ? e0 * w0 : NEG_BIG * w0;
    float v1 = (w1 > 0.f) ? e1 * w1 : NEG_BIG * w1;
    red[tid] = fmaxf(v0, v1);
    __syncthreads();
    for (int s = 128; s > 0; s >>= 1) {
        if (tid < s) red[tid] = fmaxf(red[tid], red[tid + s]);
        __syncthreads();
    }
    float mx = red[0];
    __syncthreads();
    float x0 = expf(v0 - mx), x1 = expf(v1 - mx);
    red[tid] = x0 + x1;
    __syncthreads();
    for (int s = 128; s > 0; s >>= 1) {
        if (tid < s) red[tid] += red[tid + s];
        __syncthreads();
    }
    float inv = 1.f / red[0];
    g_att[i * NND + j0] = x0 * inv;
    g_att[i * NND + j1] = x1 * inv;
}

// ---------------- x = nodes + gat_out; per-channel mean ----------------
__global__ void xmean_k() {
    int c = blockIdx.x * 128 + threadIdx.x;      // 4 x 128
    float acc = 0.f;
#pragma unroll 8
    for (int i = 0; i < NND; i++) {
        float xv = g_nodes[i * CC + c] + g_gat[i * CC + c];
        g_x[i * CC + c] = xv;
        acc += xv;
    }
    g_mean[c] = acc * (1.f / (float)NND);
}

// ---------------- SE (warp-per-row matvec) ----------------
__global__ void se_k(const float* __restrict__ w1, const float* __restrict__ w2) {
    __shared__ float mv[CC];
    __shared__ float hbuf[128];
    int tid = threadIdx.x, lane = tid & 31, wid = tid >> 5;   // 128 threads
    for (int c = tid; c < CC; c += 128) mv[c] = g_mean[c];
    __syncthreads();
    for (int r = wid; r < 128; r += 4) {
        float acc = 0.f;
        for (int c = lane; c < CC; c += 32) acc = fmaf(w1[r * CC + c], mv[c], acc);
#pragma unroll
        for (int o = 16; o > 0; o >>= 1) acc += __shfl_down_sync(0xffffffffu, acc, o);
        if (lane == 0) hbuf[r] = fmaxf(acc, 0.f);
    }
    __syncthreads();
    for (int c = tid; c < CC; c += 128) {
        float a2 = 0.f;
#pragma unroll 4
        for (int r = 0; r < 128; r++) a2 = fmaf(w2[c * 128 + r], hbuf[r], a2);
        g_y[c] = 1.f / (1.f + expf(-a2));
    }
}

// ---------------- refined = x * y; row norms ----------------
__global__ void refine_k() {
    __shared__ float red[256];
    int i = blockIdx.x, tid = threadIdx.x;       // 256 threads
    float v0 = g_x[i * CC + tid] * g_y[tid];
    float v1 = g_x[i * CC + tid + 256] * g_y[tid + 256];
    g_ref[i * CC + tid] = v0;
    g_ref[i * CC + tid + 256] = v1;
    red[tid] = v0 * v0 + v1 * v1;
    __syncthreads();
    for (int s = 128; s > 0; s >>= 1) {
        if (tid < s) red[tid] += red[tid + s];
        __syncthreads();
    }
    if (tid == 0) g_rnorm[i] = fmaxf(sqrtf(red[0]), 1e-12f);
}

// ---------------- normalize query vectors ----------------
__global__ void normq_k(const float* __restrict__ cq, const float* __restrict__ aq) {
    __shared__ float red[CC];
    int b = blockIdx.x, tid = threadIdx.x;       // 8 x 512
    const float* src = (b < KK) ? (cq + b * CC) : (aq + (b - KK) * CC);
    float* dst = (b < KK) ? (g_cqn + b * CC) : (g_aqn + (b - KK) * CC);
    float v = src[tid];
    red[tid] = v * v;
    __syncthreads();
    for (int s = 256; s > 0; s >>= 1) {
        if (tid < s) red[tid] += red[tid + s];
        __syncthreads();
    }
    dst[tid] = v / fmaxf(sqrtf(red[0]), 1e-12f);
}

// ---------------- aff[k][n] = cqn[k] . rn[n] ----------------
__global__ void aff_k() {
    int g = blockIdx.x * 8 + (threadIdx.x >> 5); // 320 blocks x 8 warps = 2560
    int lane = threadIdx.x & 31;
    int k = g / NND, n = g % NND;
    float acc = 0.f;
    for (int c = lane; c < CC; c += 32) acc = fmaf(g_cqn[k * CC + c], g_ref[n * CC + c], acc);
#pragma unroll
    for (int o = 16; o > 0; o >>= 1) acc += __shfl_down_sync(0xffffffffu, acc, o);
    if (lane == 0) g_aff[k * NND + n] = acc / g_rnorm[n];
}

// ---------------- canonical prototypes -> out[0:2560] ----------------
__global__ void canon_k(float* __restrict__ out) {
    __shared__ float w[NND];
    __shared__ float red[256];
    int k = blockIdx.x, tid = threadIdx.x;       // 256 threads
    float v0 = g_aff[k * NND + tid], v1 = g_aff[k * NND + tid + 256];
    red[tid] = fmaxf(v0, v1);
    __syncthreads();
    for (int s = 128; s > 0; s >>= 1) {
        if (tid < s) red[tid] = fmaxf(red[tid], red[tid + s]);
        __syncthreads();
    }
    float mx = red[0];
    __syncthreads();
    float e0 = expf(v0 - mx), e1 = expf(v1 - mx);
    red[tid] = e0 + e1;
    __syncthreads();
    for (int s = 128; s > 0; s >>= 1) {
        if (tid < s) red[tid] += red[tid + s];
        __syncthreads();
    }
    float inv = 1.f / red[0];
    w[tid] = e0 * inv; w[tid + 256] = e1 * inv;
    __syncthreads();
    float a0 = 0.f, a1 = 0.f;
#pragma unroll 4
    for (int n = 0; n < NND; n++) {
        float wn = w[n];
        a0 = fmaf(wn, g_ref[n * CC + tid], a0);
        a1 = fmaf(wn, g_ref[n * CC + tid + 256], a1);
    }
    out[k * CC + tid] = a0;
    out[k * CC + tid + 256] = a1;
}

// ---------------- top-32 per archetype ----------------
__global__ void top32_k() {
    __shared__ float row[NND];
    __shared__ float rv[128];
    __shared__ int   ri[128];
    int k = blockIdx.x, tid = threadIdx.x;       // 128 threads
    for (int j = tid; j < NND; j += 128) row[j] = g_aff[k * NND + j];
    __syncthreads();
    for (int t = 0; t < TOPN; t++) {
        float bv = -3.0e38f; int bi = 0x7fffffff;
        for (int j = tid; j < NND; j += 128) {
            float v = row[j];
            if (v > bv || (v == bv && j < bi)) { bv = v; bi = j; }
        }
        rv[tid] = bv; ri[tid] = bi;
        __syncthreads();
        for (int s = 64; s > 0; s >>= 1) {
            if (tid < s) {
                float ov = rv[tid + s]; int oi = ri[tid + s];
                if (ov > rv[tid] || (ov == rv[tid] && oi < ri[tid])) { rv[tid] = ov; ri[tid] = oi; }
            }
            __syncthreads();
        }
        if (tid == 0) { g_top32[k * TOPN + t] = ri[0]; row[ri[0]] = -3.0e38f; }
        __syncthreads();
    }
}

// ---------------- appearance prototypes -> out[2560:10240] ----------------
__global__ void app_k(float* __restrict__ out) {
    __shared__ int   tops[TOPN];
    __shared__ float wv[TOPN];
    __shared__ float probs[TOPN];
    int k = blockIdx.x / MMP, m = blockIdx.x % MMP;
    int tid = threadIdx.x;                        // 256 threads
    int wid = tid >> 5, lane = tid & 31;
    if (tid < TOPN) tops[tid] = g_top32[k * TOPN + tid];
    __syncthreads();
    for (int t = wid; t < TOPN; t += 8) {
        int n = tops[t];
        float acc = 0.f;
        for (int c = lane; c < CC; c += 32) acc = fmaf(g_aqn[m * CC + c], g_ref[n * CC + c], acc);
#pragma unroll
        for (int o = 16; o > 0; o >>= 1) acc += __shfl_down_sync(0xffffffffu, acc, o);
        if (lane == 0) wv[t] = acc / g_rnorm[n];
    }
    __syncthreads();
    if (tid < 32) {
        float v = wv[tid];
        float mx = v;
#pragma unroll
        for (int o = 16; o > 0; o >>= 1) mx = fmaxf(mx, __shfl_xor_sync(0xffffffffu, mx, o));
        float e = expf(v - mx);
        float s = e;
#pragma unroll
        for (int o = 16; o > 0; o >>= 1) s += __shfl_xor_sync(0xffffffffu, s, o);
        probs[tid] = e / s;
    }
    __syncthreads();
    float a0 = 0.f, a1 = 0.f;
    for (int t = 0; t < TOPN; t++) {
        int n = tops[t];
        float pb = probs[t];
        a0 = fmaf(pb, g_ref[n * CC + tid], a0);
        a1 = fmaf(pb, g_ref[n * CC + tid + 256], a1);
    }
    int base = KK * CC + (k * MMP + m) * CC;
    out[base + tid] = a0;
    out[base + tid + 256] = a1;
}

__global__ void tail_k(float* __restrict__ out, int out_size) {
    if (out_size > KK * CC + KK * MMP * CC) out[KK * CC + KK * MMP * CC] = 0.f;
}

// ---------------- launcher ----------------
extern "C" void kernel_launch(void* const* d_in, const int* in_sizes, int n_in,
                              void* d_out, int out_size) {
    const float* feat = (const float*)d_in[0];
    const float* cq   = (const float*)d_in[3];
    const float* aq   = (const float*)d_in[4];
    const float* gatW = (const float*)d_in[5];
    const float* gata = (const float*)d_in[6];
    const float* sew1 = (const float*)d_in[7];
    const float* sew2 = (const float*)d_in[8];
    float* out = (float*)d_out;

    float *p_nn, *p_sim, *p_nodes, *p_Wh, *p_att, *p_gat;
    cudaGetSymbolAddress((void**)&p_nn, g_nn);
    cudaGetSymbolAddress((void**)&p_sim, g_sim);
    cudaGetSymbolAddress((void**)&p_nodes, g_nodes);
    cudaGetSymbolAddress((void**)&p_Wh, g_Wh);
    cudaGetSymbolAddress((void**)&p_att, g_att);
    cudaGetSymbolAddress((void**)&p_gat, g_gat);

    cudaFuncSetAttribute(fps_kernel, cudaFuncAttributeMaxDynamicSharedMemorySize, SC_BYTES);

    dim3 g64(8, 8);

    // launch order tuned so ncu's capture slot hits fps_kernel
    fps_init<<<1, 1>>>();
    dummy_k<<<1, 1>>>();
    dummy_k<<<1, 1>>>();
    fps_kernel<<<NBLK, 512, SC_BYTES>>>(feat);
    gather_nodes<<<NND, 512>>>(feat);
    gemm_nt64<<<g64, 256>>>(p_nn, p_nn, p_sim);
    topk10_k<<<NND, 128>>>();
    adj_build<<<dim3(NND, 2), 256>>>();
    gemm_nt64<<<g64, 256>>>(p_nodes, gatW, p_Wh);
    f12_k<<<64, 256>>>(gata);
    att_row<<<NND, 256>>>();
    gemm_nn64<<<g64, 256>>>(p_att, p_Wh, p_gat);
    xmean_k<<<4, 128>>>();
    se_k<<<1, 128>>>(sew1, sew2);
    refine_k<<<NND, 256>>>();
    normq_k<<<8, 512>>>(cq, aq);
    aff_k<<<320, 256>>>();
    canon_k<<<KK, 256>>>(out);
    top32_k<<<KK, 128>>>();
    app_k<<<KK * MMP, 256>>>(out);
    tail_k<<<1, 1>>>(out, out_size);
}